// round 12
// baseline (speedup 1.0000x reference)
#include <cuda_runtime.h>

// CTC forward scan split at T/2 (fwd + mirrored bwd halves on separate CTAs),
// combine = -LSE_m(F[m]+B[m]) * ln2 / T.
// TWO-STEP FUSION: f''[p] = lae3(S2+f[p], M1[sj(p)]+f[p-1], M2[sj(p-1),sj(p)]+f[p-2]).
// Coefs (S2, M1[4], M2[16]) per step-pair staged in a 16-slab smem ring, sourced
// straight from gmem registers; ONE barrier per epoch.
// NEW vs R11: inner-loop lae3 uses ex2+ex2 followed by a degree-5 polynomial
// log2 with exact power-of-two range reduction — no lg2 MUFU in the main loop
// (MUFU per warp-iter 6 -> 4). Staging & combine keep accurate MUFU lae2/lg2.

#define T_STEPS   4096
#define T_HALF    2048
#define BATCH     64
#define NFEAT     5
#define P_POS     512
#define NEG_LARGE (-1e30f)
#define K_EPOCH   32
#define NITER     16                      // fused iterations per chunk
#define NCHUNK    (T_HALF / K_EPOCH)      // 64
#define NTHREADS  256
#define NWARPS    8
#define NEPOCH    (NCHUNK + NWARPS - 1)   // 71
#define GSTRIDE   24                      // S2, M1[4], M2[16], pad
#define CSTRIDE   (NITER * GSTRIDE)       // 384 floats per chunk slab
#define NCSLAB    16
#define L2E       1.4426950408889634f
#define LN2F      0.6931471805599453f

__device__ float g_scrF[BATCH * (P_POS + 1)];
__device__ float g_scrB[BATCH * (P_POS + 1)];

__device__ __forceinline__ float ex2f(float v){ float r; asm("ex2.approx.f32 %0,%1;" : "=f"(r) : "f"(v)); return r; }
__device__ __forceinline__ float lg2f(float v){ float r; asm("lg2.approx.f32 %0,%1;" : "=f"(r) : "f"(v)); return r; }

// accurate 2-MUFU logaddexp (log2 domain) — staging only
__device__ __forceinline__ float lae2(float a, float b) {
    float m = fmaxf(a, b);
    float d = -fabsf(a - b);
    return m + lg2f(1.0f + ex2f(d));
}

// 3-way logaddexp (log2 domain), poly-log2 version (no lg2 MUFU):
//   y = 1 + ex2(u1-m) + ex2(v-m) in [1,3]; exact range-reduce to [1,2),
//   then degree-5 polynomial (max abs err ~5e-5; R9-validated coefficients).
__device__ __forceinline__ float lae3p(float a, float b, float c) {
    float u1 = fminf(a, b);
    float u2 = fmaxf(a, b);
    float m  = fmaxf(u2, c);
    float v  = fminf(u2, c);
    float y  = 1.0f + (ex2f(u1 - m) + ex2f(v - m));     // [1,3]
    bool  hi = (y >= 2.0f);
    float t  = hi ? (y * 0.5f) : y;                     // [1,2)
    float base = hi ? (m + 1.0f) : m;                   // fold +n into m (parallel)
    float u = fmaf(2.0f, t, -3.0f);                     // poly var on [-1,1]
    float p = fmaf(u, 0.00135227f, -0.0049475038f);
    p = fmaf(u, p,  0.0177286f);
    p = fmaf(u, p, -0.0799641965f);
    p = fmaf(u, p,  0.4809086f);
    p = fmaf(u, p,  0.5849121935f);
    return base + p;
}

__global__ void __launch_bounds__(NTHREADS, 1)
ctc_half_kernel(const float* __restrict__ x,
                const int*   __restrict__ seqs,
                const int*   __restrict__ seqlens)
{
    const bool fwdDir = (blockIdx.x & 1) == 0;
    const int  b      = blockIdx.x >> 1;
    const int  tid    = threadIdx.x;
    const int  lane   = tid & 31;
    const int  w      = tid >> 5;

    __shared__ float  cof[NCSLAB * CSTRIDE];   // fused coefs per chunk (ring)
    __shared__ float2 bnd[2][NWARPS][NITER];   // lane31 (f0,f1) entering iter k

    const float* xb = x + b * NFEAT;           // x[t*B*F + b*F + f]
    const int    TB = BATCH * NFEAT;

    // ---- per-thread coef staging assignment: group g, slot j ----
    // out0 -> gb[j]:  j==0: S2 | j in 1..4: M1[j-1] | j in 5..15: M2[j-5]
    // out1 -> gb[16+j] (j<=4 only): M2[11+j]
    const int g  = tid >> 4;
    const int j  = tid & 15;
    const bool hasOut1 = (j <= 4);
    int fa0, fa1; bool isM1 = false;
    if (j == 0)      { fa0 = 4; fa1 = 4; }
    else if (j <= 4) { fa0 = j - 1; fa1 = j - 1; isM1 = true; }
    else             { int ei = j - 5; fa0 = ei >> 2; fa1 = ei & 3; }
    const int fb0 = (11 + j) >> 2;
    const int fb1 = (11 + j) & 3;

    // ---- per-lane recurrence setup ----
    const int pb = (w << 6) + (lane << 1);     // lane owns positions pb+1, pb+2
    const int* sp = seqs + b * P_POS;
    int si0, si1, idxA;                        // sj(p0), sj(p1), sj(p0-1)
    if (fwdDir) {
        si0  = sp[pb];
        si1  = sp[pb + 1];
        idxA = (pb == 0) ? 0 : sp[pb - 1];
    } else {
        si0  = sp[P_POS - 1 - pb];
        si1  = sp[P_POS - 2 - pb];
        idxA = (pb == 0) ? 0 : sp[P_POS - pb];
    }
    const int m1o0 = 1 + si0;
    const int m1o1 = 1 + si1;
    const int m2o0 = 5 + idxA * 4 + si0;
    const int m2o1 = 5 + si0  * 4 + si1;

    const int q0 = P_POS - seqlens[b];
    float f0, f1, fz;
    if (fwdDir) {
        f0 = f1 = NEG_LARGE; fz = 0.0f;
    } else {
        f0 = (pb + 1 == q0) ? 0.f : NEG_LARGE;
        f1 = (pb + 2 == q0) ? 0.f : NEG_LARGE;
        fz = (q0 == 0) ? 0.f : NEG_LARGE;
    }

    for (int i = tid; i < 2 * NWARPS * NITER; i += NTHREADS)
        (&bnd[0][0][0])[i] = make_float2(NEG_LARGE, NEG_LARGE);

    #define GTIME(s) (fwdDir ? (s) : (T_STEPS - 1 - (s)))

    // ---- prologue: stage coefs for chunk 0 into slab 0 ----
    {
        const int s0 = 2 * g, s1 = 2 * g + 1;
        const long o0 = (long)GTIME(s0) * TB, o1 = (long)GTIME(s1) * TB;
        float a0 = xb[o0 + fa0] * L2E;
        float a1 = xb[o1 + fa1] * L2E;
        float st0 = 0.f, st1 = 0.f, b0v = 0.f, b1v = 0.f;
        if (isM1) { st0 = xb[o0 + 4] * L2E; st1 = xb[o1 + 4] * L2E; }
        if (hasOut1) { b0v = xb[o0 + fb0] * L2E; b1v = xb[o1 + fb1] * L2E; }
        float* gb = cof + g * GSTRIDE;
        gb[j] = isM1 ? lae2(a0 + st1, st0 + a1) : (a0 + a1);
        if (hasOut1) gb[16 + j] = b0v + b1v;
    }
    __syncthreads();

    for (int e = 0; e < NEPOCH; ++e) {
        // ---- issue LDGs for chunk e+1 coef inputs (hidden under compute) ----
        float a0 = 0.f, a1 = 0.f, st0 = 0.f, st1 = 0.f, b0v = 0.f, b1v = 0.f;
        const bool pf = (e + 1) < NCHUNK;
        if (pf) {
            const int s0 = (e + 1) * K_EPOCH + 2 * g, s1 = s0 + 1;
            const long o0 = (long)GTIME(s0) * TB, o1 = (long)GTIME(s1) * TB;
            a0 = xb[o0 + fa0] * L2E;
            a1 = xb[o1 + fa1] * L2E;
            if (isM1) { st0 = xb[o0 + 4] * L2E; st1 = xb[o1 + 4] * L2E; }
            if (hasOut1) { b0v = xb[o0 + fb0] * L2E; b1v = xb[o1 + fb1] * L2E; }
        }

        const int  c     = e - w;
        const bool valid = (c >= 0) && (c < NCHUNK);

        if (valid) {
            const float*  cs = cof + (c & (NCSLAB - 1)) * CSTRIDE;
            const float2* bR = bnd[(e & 1) ^ 1][(w > 0) ? (w - 1) : 0];
            float2*       bW = &bnd[e & 1][w][0];

            #pragma unroll
            for (int k = 0; k < NITER; ++k) {
                const float* gb  = cs + k * GSTRIDE;
                float S2  = gb[0];
                float M1a = gb[m1o0];
                float M1b = gb[m1o1];
                float M2a = gb[m2o0];
                float M2b = gb[m2o1];
                float2 bv = bR[k];

                float Lf0 = __shfl_up_sync(0xffffffffu, f0, 1);
                float Lf1 = __shfl_up_sync(0xffffffffu, f1, 1);
                if (lane == 0) {
                    Lf0 = (w == 0) ? NEG_LARGE : bv.x;
                    Lf1 = (w == 0) ? fz        : bv.y;
                }
                if (lane == 31) bW[k] = make_float2(f0, f1);

                float A0 = S2 + f0;
                float B0 = M1a + Lf1;
                float C0 = M2a + Lf0;
                float A1 = S2 + f1;
                float B1 = M1b + f0;     // old f0
                float C1 = M2b + Lf1;
                if (w == 0) fz += S2;

                f0 = lae3p(A0, B0, C0);
                f1 = lae3p(A1, B1, C1);
            }
        }

        // ---- compute + commit coefs for chunk e+1 ----
        if (pf) {
            float* gb = cof + ((e + 1) & (NCSLAB - 1)) * CSTRIDE + g * GSTRIDE;
            gb[j] = isM1 ? lae2(a0 + st1, st0 + a1) : (a0 + a1);
            if (hasOut1) gb[16 + j] = b0v + b1v;
        }
        __syncthreads();
    }

    // ---- epilogue: write half-result. fwd: index = position; bwd: m = P - q. ----
    float* scr = fwdDir ? (g_scrF + b * (P_POS + 1)) : (g_scrB + b * (P_POS + 1));
    if (fwdDir) {
        scr[pb + 1] = f0; scr[pb + 2] = f1;
        if (tid == 0) scr[0] = fz;
    } else {
        scr[P_POS - (pb + 1)] = f0;
        scr[P_POS - (pb + 2)] = f1;
        if (tid == 0) scr[P_POS] = fz;
    }
}

__global__ void __launch_bounds__(128)
ctc_combine_kernel(float* __restrict__ out)
{
    const int b    = blockIdx.x;
    const int tid  = threadIdx.x;
    const int lane = tid & 31;
    const int w    = tid >> 5;
    __shared__ float red[4];

    const float* F = g_scrF + b * (P_POS + 1);
    const float* B = g_scrB + b * (P_POS + 1);

    float vm = -3e38f;
    float v[5];
    int   nv = 0;
    for (int p = tid; p <= P_POS; p += 128) {
        float t = F[p] + B[p];
        v[nv++] = t;
        vm = fmaxf(vm, t);
    }
    #pragma unroll
    for (int off = 16; off; off >>= 1)
        vm = fmaxf(vm, __shfl_xor_sync(0xffffffffu, vm, off));
    if (lane == 0) red[w] = vm;
    __syncthreads();
    vm = fmaxf(fmaxf(red[0], red[1]), fmaxf(red[2], red[3]));

    float s = 0.f;
    for (int i = 0; i < nv; ++i) s += ex2f(v[i] - vm);
    #pragma unroll
    for (int off = 16; off; off >>= 1)
        s += __shfl_xor_sync(0xffffffffu, s, off);
    __syncthreads();
    if (lane == 0) red[w] = s;
    __syncthreads();
    if (tid == 0) {
        float st = red[0] + red[1] + red[2] + red[3];
        float lse = vm + lg2f(st);
        out[b] = -lse * (LN2F / (float)T_STEPS);
    }
}

extern "C" void kernel_launch(void* const* d_in, const int* in_sizes, int n_in,
                              void* d_out, int out_size)
{
    const float* x       = (const float*)d_in[0];
    const int*   seqs    = (const int*)  d_in[1];
    const int*   seqlens = (const int*)  d_in[2];
    float*       out     = (float*)      d_out;

    ctc_half_kernel<<<2 * BATCH, NTHREADS>>>(x, seqs, seqlens);
    ctc_combine_kernel<<<BATCH, 128>>>(out);
}

// round 13
// speedup vs baseline: 1.8068x; 1.8068x over previous
#include <cuda_runtime.h>

// CTC forward scan split at T/2 (fwd + mirrored bwd halves on separate CTAs),
// combine = -LSE_m(F[m]+B[m]) * ln2 / T.
// TWO-STEP FUSION: f''[p] = lae3(S2+f[p], M1[sj(p)]+f[p-1], M2[sj(p-1),sj(p)]+f[p-2]).
// Coefs (S2, M1[4], M2[16]) per step-pair in an 8-slab smem ring, sourced from
// gmem registers; ONE barrier per epoch. Exact 2-MUFU lae3 (R11 math).
// NEW vs R11: 128 threads = 4 warps (1/SMSP), lane owns 4 consecutive positions.
// Halves MIO ops and issue load per position-step; 3 of 4 lae3 chains per lane
// are intra-thread. Skew depth 8 -> 4 (NEPOCH 71 -> 67).

#define T_STEPS   4096
#define T_HALF    2048
#define BATCH     64
#define NFEAT     5
#define P_POS     512
#define NEG_LARGE (-1e30f)
#define K_EPOCH   32
#define NITER     16                      // fused iterations per chunk
#define NCHUNK    (T_HALF / K_EPOCH)      // 64
#define NTHREADS  128
#define NWARPS    4
#define NEPOCH    (NCHUNK + NWARPS - 1)   // 67
#define GSTRIDE   24                      // S2, M1[4], M2[16], pad
#define CSTRIDE   (NITER * GSTRIDE)       // 384 floats per chunk slab
#define NCSLAB    8
#define L2E       1.4426950408889634f
#define LN2F      0.6931471805599453f

__device__ float g_scrF[BATCH * (P_POS + 1)];
__device__ float g_scrB[BATCH * (P_POS + 1)];

__device__ __forceinline__ float ex2f(float v){ float r; asm("ex2.approx.f32 %0,%1;" : "=f"(r) : "f"(v)); return r; }
__device__ __forceinline__ float lg2f(float v){ float r; asm("lg2.approx.f32 %0,%1;" : "=f"(r) : "f"(v)); return r; }

// accurate 2-MUFU logaddexp (log2 domain) — staging only
__device__ __forceinline__ float lae2(float a, float b) {
    float m = fmaxf(a, b);
    float d = -fabsf(a - b);
    return m + lg2f(1.0f + ex2f(d));
}

// 3-way logaddexp (log2 domain): max term's ex2 (==1) skipped via sort. Exact MUFU.
__device__ __forceinline__ float lae3(float a, float b, float c) {
    float u1 = fminf(a, b);
    float u2 = fmaxf(a, b);
    float m  = fmaxf(u2, c);
    float v  = fminf(u2, c);
    float y  = 1.0f + (ex2f(u1 - m) + ex2f(v - m));
    return m + lg2f(y);
}

// coef entry -> feature indices. entry 0: S2; 1..4: M1[e-1]; 5..20: M2[e-5].
__device__ __forceinline__ int entFA(int e){ return (e == 0) ? 4 : (e <= 4 ? e - 1 : ((e - 5) >> 2)); }
__device__ __forceinline__ int entFB(int e){ return (e == 0) ? 4 : (e <= 4 ? e - 1 : ((e - 5) & 3)); }

__global__ void __launch_bounds__(NTHREADS, 1)
ctc_half_kernel(const float* __restrict__ x,
                const int*   __restrict__ seqs,
                const int*   __restrict__ seqlens)
{
    const bool fwdDir = (blockIdx.x & 1) == 0;
    const int  b      = blockIdx.x >> 1;
    const int  tid    = threadIdx.x;
    const int  lane   = tid & 31;
    const int  w      = tid >> 5;

    __shared__ float  cof[NCSLAB * CSTRIDE];   // fused coefs per chunk (ring)
    __shared__ float2 bnd[2][NWARPS][NITER];   // lane31 (f2,f3) entering iter k

    const float* xb = x + b * NFEAT;           // x[t*B*F + b*F + f]
    const int    TB = BATCH * NFEAT;

    // ---- coef staging assignment: group g (16), slot j (8) ----
    // thread j covers entries {j, j+8, j+16(if j<=4)} — union is 0..20, complete.
    const int g  = tid >> 3;
    const int j  = tid & 7;
    const int e0_ = j, e1_ = j + 8, e2_ = (j <= 4) ? (j + 16) : -1;
    const bool m1f = (j >= 1 && j <= 4);       // e0_ is an M1 entry
    const int fa0 = entFA(e0_), fb0 = entFB(e0_);
    const int fa1 = entFA(e1_), fb1 = entFB(e1_);
    const int fa2 = (e2_ >= 0) ? entFA(e2_) : 0, fb2 = (e2_ >= 0) ? entFB(e2_) : 0;

    // ---- per-lane recurrence setup: lane owns positions pb+1 .. pb+4 ----
    const int pb = (w << 7) + (lane << 2);
    const int* sp = seqs + b * P_POS;
    int s0i, s1i, s2i, s3i, idxA;              // sj(p0..p3), sj(p0-1)
    if (fwdDir) {
        s0i = sp[pb];     s1i = sp[pb + 1];
        s2i = sp[pb + 2]; s3i = sp[pb + 3];
        idxA = (pb == 0) ? 0 : sp[pb - 1];
    } else {
        s0i = sp[P_POS - 1 - pb]; s1i = sp[P_POS - 2 - pb];
        s2i = sp[P_POS - 3 - pb]; s3i = sp[P_POS - 4 - pb];
        idxA = (pb == 0) ? 0 : sp[P_POS - pb];
    }
    const int m1o0 = 1 + s0i, m1o1 = 1 + s1i, m1o2 = 1 + s2i, m1o3 = 1 + s3i;
    const int m2o0 = 5 + idxA * 4 + s0i;
    const int m2o1 = 5 + s0i  * 4 + s1i;
    const int m2o2 = 5 + s1i  * 4 + s2i;
    const int m2o3 = 5 + s2i  * 4 + s3i;

    const int q0 = P_POS - seqlens[b];
    float f0, f1, f2, f3, fz;
    if (fwdDir) {
        f0 = f1 = f2 = f3 = NEG_LARGE; fz = 0.0f;
    } else {
        f0 = (pb + 1 == q0) ? 0.f : NEG_LARGE;
        f1 = (pb + 2 == q0) ? 0.f : NEG_LARGE;
        f2 = (pb + 3 == q0) ? 0.f : NEG_LARGE;
        f3 = (pb + 4 == q0) ? 0.f : NEG_LARGE;
        fz = (q0 == 0) ? 0.f : NEG_LARGE;
    }

    for (int i = tid; i < 2 * NWARPS * NITER; i += NTHREADS)
        (&bnd[0][0][0])[i] = make_float2(NEG_LARGE, NEG_LARGE);

    #define GTIME(s) (fwdDir ? (s) : (T_STEPS - 1 - (s)))

    // ---- prologue: stage coefs for chunk 0 into slab 0 ----
    {
        const int s0 = 2 * g, s1 = 2 * g + 1;
        const long o0 = (long)GTIME(s0) * TB, o1 = (long)GTIME(s1) * TB;
        float a0 = xb[o0 + fa0] * L2E, a1 = xb[o1 + fb0] * L2E;
        float b0 = xb[o0 + fa1] * L2E, b1 = xb[o1 + fb1] * L2E;
        float c0 = 0.f, c1 = 0.f, st0 = 0.f, st1 = 0.f;
        if (e2_ >= 0) { c0 = xb[o0 + fa2] * L2E; c1 = xb[o1 + fb2] * L2E; }
        if (m1f)      { st0 = xb[o0 + 4] * L2E;  st1 = xb[o1 + 4] * L2E; }
        float* gb = cof + g * GSTRIDE;
        gb[e0_] = m1f ? lae2(a0 + st1, st0 + a1) : (a0 + a1);
        gb[e1_] = b0 + b1;
        if (e2_ >= 0) gb[e2_] = c0 + c1;
    }
    __syncthreads();

    for (int e = 0; e < NEPOCH; ++e) {
        // ---- issue LDGs for chunk e+1 coef inputs (hidden under compute) ----
        float a0 = 0.f, a1 = 0.f, b0 = 0.f, b1 = 0.f, c0 = 0.f, c1 = 0.f, st0 = 0.f, st1 = 0.f;
        const bool pf = (e + 1) < NCHUNK;
        if (pf) {
            const int s0 = (e + 1) * K_EPOCH + 2 * g, s1 = s0 + 1;
            const long o0 = (long)GTIME(s0) * TB, o1 = (long)GTIME(s1) * TB;
            a0 = xb[o0 + fa0] * L2E; a1 = xb[o1 + fb0] * L2E;
            b0 = xb[o0 + fa1] * L2E; b1 = xb[o1 + fb1] * L2E;
            if (e2_ >= 0) { c0 = xb[o0 + fa2] * L2E; c1 = xb[o1 + fb2] * L2E; }
            if (m1f)      { st0 = xb[o0 + 4] * L2E;  st1 = xb[o1 + 4] * L2E; }
        }

        const int  c     = e - w;
        const bool valid = (c >= 0) && (c < NCHUNK);

        if (valid) {
            const float*  cs = cof + (c & (NCSLAB - 1)) * CSTRIDE;
            const float2* bR = bnd[(e & 1) ^ 1][(w > 0) ? (w - 1) : 0];
            float2*       bW = &bnd[e & 1][w][0];

            #pragma unroll
            for (int k = 0; k < NITER; ++k) {
                const float* gb = cs + k * GSTRIDE;
                float S2  = gb[0];
                float M1a = gb[m1o0], M1b = gb[m1o1], M1c = gb[m1o2], M1d = gb[m1o3];
                float M2a = gb[m2o0], M2b = gb[m2o1], M2c = gb[m2o2], M2d = gb[m2o3];
                float2 bv = bR[k];

                float Lf3 = __shfl_up_sync(0xffffffffu, f3, 1);   // f[pb]
                float Lf2 = __shfl_up_sync(0xffffffffu, f2, 1);   // f[pb-1]
                if (lane == 0) {
                    Lf3 = (w == 0) ? fz        : bv.y;
                    Lf2 = (w == 0) ? NEG_LARGE : bv.x;
                }
                if (lane == 31) bW[k] = make_float2(f2, f3);

                float A0 = S2 + f0, B0 = M1a + Lf3, C0 = M2a + Lf2;
                float A1 = S2 + f1, B1 = M1b + f0,  C1 = M2b + Lf3;
                float A2 = S2 + f2, B2 = M1c + f1,  C2 = M2c + f0;
                float A3 = S2 + f3, B3 = M1d + f2,  C3 = M2d + f1;
                if (w == 0) fz += S2;

                f0 = lae3(A0, B0, C0);
                f1 = lae3(A1, B1, C1);
                f2 = lae3(A2, B2, C2);
                f3 = lae3(A3, B3, C3);
            }
        }

        // ---- compute + commit coefs for chunk e+1 ----
        if (pf) {
            float* gb = cof + ((e + 1) & (NCSLAB - 1)) * CSTRIDE + g * GSTRIDE;
            gb[e0_] = m1f ? lae2(a0 + st1, st0 + a1) : (a0 + a1);
            gb[e1_] = b0 + b1;
            if (e2_ >= 0) gb[e2_] = c0 + c1;
        }
        __syncthreads();
    }

    // ---- epilogue: write half-result. fwd: index = position; bwd: m = P - q. ----
    float* scr = fwdDir ? (g_scrF + b * (P_POS + 1)) : (g_scrB + b * (P_POS + 1));
    if (fwdDir) {
        scr[pb + 1] = f0; scr[pb + 2] = f1; scr[pb + 3] = f2; scr[pb + 4] = f3;
        if (tid == 0) scr[0] = fz;
    } else {
        scr[P_POS - (pb + 1)] = f0;
        scr[P_POS - (pb + 2)] = f1;
        scr[P_POS - (pb + 3)] = f2;
        scr[P_POS - (pb + 4)] = f3;
        if (tid == 0) scr[P_POS] = fz;
    }
}

__global__ void __launch_bounds__(128)
ctc_combine_kernel(float* __restrict__ out)
{
    const int b    = blockIdx.x;
    const int tid  = threadIdx.x;
    const int lane = tid & 31;
    const int w    = tid >> 5;
    __shared__ float red[4];

    const float* F = g_scrF + b * (P_POS + 1);
    const float* B = g_scrB + b * (P_POS + 1);

    float vm = -3e38f;
    float v[5];
    int   nv = 0;
    for (int p = tid; p <= P_POS; p += 128) {
        float t = F[p] + B[p];
        v[nv++] = t;
        vm = fmaxf(vm, t);
    }
    #pragma unroll
    for (int off = 16; off; off >>= 1)
        vm = fmaxf(vm, __shfl_xor_sync(0xffffffffu, vm, off));
    if (lane == 0) red[w] = vm;
    __syncthreads();
    vm = fmaxf(fmaxf(red[0], red[1]), fmaxf(red[2], red[3]));

    float s = 0.f;
    for (int i = 0; i < nv; ++i) s += ex2f(v[i] - vm);
    #pragma unroll
    for (int off = 16; off; off >>= 1)
        s += __shfl_xor_sync(0xffffffffu, s, off);
    __syncthreads();
    if (lane == 0) red[w] = s;
    __syncthreads();
    if (tid == 0) {
        float st = red[0] + red[1] + red[2] + red[3];
        float lse = vm + lg2f(st);
        out[b] = -lse * (LN2F / (float)T_STEPS);
    }
}

extern "C" void kernel_launch(void* const* d_in, const int* in_sizes, int n_in,
                              void* d_out, int out_size)
{
    const float* x       = (const float*)d_in[0];
    const int*   seqs    = (const int*)  d_in[1];
    const int*   seqlens = (const int*)  d_in[2];
    float*       out     = (float*)      d_out;

    ctc_half_kernel<<<2 * BATCH, NTHREADS>>>(x, seqs, seqlens);
    ctc_combine_kernel<<<BATCH, 128>>>(out);
}